// round 1
// baseline (speedup 1.0000x reference)
#include <cuda_runtime.h>
#include <math.h>

#define S_LEN 1024
#define D_DIM 4096
#define NH 32
#define NKV 8
#define HD 128
#define FETCH_MAX 204

// -------- scratch (device globals: allocation-free) --------
__device__ float g_Q[(size_t)S_LEN * D_DIM];            // [t][h*128+d]
__device__ float g_K[(size_t)S_LEN * NKV * HD];         // [t][kv*128+d]
__device__ float g_V[(size_t)S_LEN * NKV * HD];
__device__ float g_P[(size_t)NH * S_LEN * S_LEN];       // scores -> probs in place
__device__ float g_AO[(size_t)S_LEN * D_DIM];           // attention output [t][h*128+d]
__device__ int   g_fetch[S_LEN];

// =============== GEMM: C = alpha * A(MxK) * B(NxK)^T ===============
__global__ void __launch_bounds__(256) sgemm_abT(
    const float* __restrict__ A, int lda, long long sA,
    const float* __restrict__ B, int ldb, long long sB, int zdivB,
    float* __restrict__ C, int ldc, long long sC,
    int M, int N, int K, float alpha)
{
    A += (long long)blockIdx.z * sA;
    B += (long long)(blockIdx.z / zdivB) * sB;
    C += (long long)blockIdx.z * sC;
    __shared__ __align__(16) float As[16][64];
    __shared__ __align__(16) float Bs[16][64];
    int tid = threadIdx.x;
    int tx = tid & 15, ty = tid >> 4;
    int lr = tid >> 2, lc = (tid & 3) << 2;
    int m0 = blockIdx.y * 64, n0 = blockIdx.x * 64;
    float acc[4][4] = {};
    for (int k0 = 0; k0 < K; k0 += 16) {
        float4 a = *(const float4*)(A + (size_t)(m0 + lr) * lda + k0 + lc);
        As[lc + 0][lr] = a.x; As[lc + 1][lr] = a.y; As[lc + 2][lr] = a.z; As[lc + 3][lr] = a.w;
        float4 b = *(const float4*)(B + (size_t)(n0 + lr) * ldb + k0 + lc);
        Bs[lc + 0][lr] = b.x; Bs[lc + 1][lr] = b.y; Bs[lc + 2][lr] = b.z; Bs[lc + 3][lr] = b.w;
        __syncthreads();
        #pragma unroll
        for (int kk = 0; kk < 16; kk++) {
            float4 av = *(const float4*)&As[kk][ty << 2];
            float4 bv = *(const float4*)&Bs[kk][tx << 2];
            float aa[4] = {av.x, av.y, av.z, av.w};
            float bb[4] = {bv.x, bv.y, bv.z, bv.w};
            #pragma unroll
            for (int i = 0; i < 4; i++)
                #pragma unroll
                for (int j = 0; j < 4; j++) acc[i][j] += aa[i] * bb[j];
        }
        __syncthreads();
    }
    #pragma unroll
    for (int i = 0; i < 4; i++) {
        float4 r = make_float4(acc[i][0] * alpha, acc[i][1] * alpha,
                               acc[i][2] * alpha, acc[i][3] * alpha);
        *(float4*)(C + (size_t)(m0 + (ty << 2) + i) * ldc + n0 + (tx << 2)) = r;
    }
}

// =============== GEMM: C = alpha * A(MxK) * B(KxN) ===============
__global__ void __launch_bounds__(256) sgemm_ab(
    const float* __restrict__ A, int lda, long long sA,
    const float* __restrict__ B, int ldb, long long sB, int zdivB,
    float* __restrict__ C, int ldc, long long sC,
    int M, int N, int K, float alpha)
{
    A += (long long)blockIdx.z * sA;
    B += (long long)(blockIdx.z / zdivB) * sB;
    C += (long long)blockIdx.z * sC;
    __shared__ __align__(16) float As[16][64];
    __shared__ __align__(16) float Bs[16][64];
    int tid = threadIdx.x;
    int tx = tid & 15, ty = tid >> 4;
    int lr = tid >> 2, lc = (tid & 3) << 2;   // A loader
    int kr = tid >> 4, nc = (tid & 15) << 2;  // B loader
    int m0 = blockIdx.y * 64, n0 = blockIdx.x * 64;
    float acc[4][4] = {};
    for (int k0 = 0; k0 < K; k0 += 16) {
        float4 a = *(const float4*)(A + (size_t)(m0 + lr) * lda + k0 + lc);
        As[lc + 0][lr] = a.x; As[lc + 1][lr] = a.y; As[lc + 2][lr] = a.z; As[lc + 3][lr] = a.w;
        float4 b = *(const float4*)(B + (size_t)(k0 + kr) * ldb + n0 + nc);
        *(float4*)&Bs[kr][nc] = b;
        __syncthreads();
        #pragma unroll
        for (int kk = 0; kk < 16; kk++) {
            float4 av = *(const float4*)&As[kk][ty << 2];
            float4 bv = *(const float4*)&Bs[kk][tx << 2];
            float aa[4] = {av.x, av.y, av.z, av.w};
            float bb[4] = {bv.x, bv.y, bv.z, bv.w};
            #pragma unroll
            for (int i = 0; i < 4; i++)
                #pragma unroll
                for (int j = 0; j < 4; j++) acc[i][j] += aa[i] * bb[j];
        }
        __syncthreads();
    }
    #pragma unroll
    for (int i = 0; i < 4; i++) {
        float4 r = make_float4(acc[i][0] * alpha, acc[i][1] * alpha,
                               acc[i][2] * alpha, acc[i][3] * alpha);
        *(float4*)(C + (size_t)(m0 + (ty << 2) + i) * ldc + n0 + (tx << 2)) = r;
    }
}

// =============== RoPE (in place) ===============
__global__ void rope_kernel(float* __restrict__ X, int nheads,
                            const float* __restrict__ cosb, const float* __restrict__ sinb)
{
    int t = blockIdx.x, h = blockIdx.y, d = threadIdx.x; // 64 threads
    float* p = X + ((size_t)t * nheads + h) * HD;
    float x1 = p[d], x2 = p[d + 64];
    float c1 = cosb[t * HD + d],      s1 = sinb[t * HD + d];
    float c2 = cosb[t * HD + d + 64], s2 = sinb[t * HD + d + 64];
    p[d]      = x1 * c1 - x2 * s1;
    p[d + 64] = x2 * c2 + x1 * s2;
}

// =============== per-row fetch_num ===============
__global__ void __launch_bounds__(256) stats_kernel(const float* __restrict__ P,
                                                    int* __restrict__ fetch)
{
    int t = blockIdx.x, tid = threadIdx.x;
    int len = t + 1;
    __shared__ float sf[256];
    __shared__ int si[256];
    const float* row0 = P + (size_t)t * S_LEN;   // head 0, causal row max
    float m = -3.4e38f;
    for (int s = tid; s < len; s += 256) m = fmaxf(m, row0[s]);
    sf[tid] = m; __syncthreads();
    for (int off = 128; off > 0; off >>= 1) { if (tid < off) sf[tid] = fmaxf(sf[tid], sf[tid + off]); __syncthreads(); }
    float thr = sf[0] - 5.0f;
    int cnt = 0;
    for (int h = 0; h < NH; h++) {
        const float* row = P + ((size_t)h * S_LEN + t) * S_LEN;
        for (int s = tid; s < len; s += 256) cnt += (row[s] >= thr) ? 1 : 0;
    }
    si[tid] = cnt; __syncthreads();
    for (int off = 128; off > 0; off >>= 1) { if (tid < off) si[tid] += si[tid + off]; __syncthreads(); }
    if (tid == 0) {
        int f = si[0] >> 5;            // floor(mean over 32 heads)
        fetch[t] = f < FETCH_MAX ? f : FETCH_MAX;
    }
}

__device__ __forceinline__ unsigned fkey(float f) {
    unsigned u = __float_as_uint(f);
    return (u & 0x80000000u) ? ~u : (u | 0x80000000u); // monotone float->uint
}

// =============== fused radix-select top-k + softmax (probs in place) ===============
__global__ void __launch_bounds__(256) softmax_select(float* __restrict__ P,
                                                      const int* __restrict__ fetch)
{
    int t = blockIdx.x, h = blockIdx.y, tid = threadIdx.x;
    float* row = P + ((size_t)h * S_LEN + t) * S_LEN;
    __shared__ float sf[256];
    __shared__ unsigned hist[256];
    __shared__ unsigned s_sel;
    __shared__ int s_kk, s_cut;

    int len = t + 1;
    bool do_topk = false;
    int k = 0;
    if (t >= FETCH_MAX) {
        k = fetch[t];
        if (k == 0) len = S_LEN;       // all-NEG mask => softmax over full row
        else do_topk = true;           // k < len always here (k<=204 < t+1)
    }

    float m = -3.4e38f;
    for (int s = tid; s < len; s += 256) m = fmaxf(m, row[s]);
    sf[tid] = m; __syncthreads();
    for (int off = 128; off > 0; off >>= 1) { if (tid < off) sf[tid] = fmaxf(sf[tid], sf[tid + off]); __syncthreads(); }
    float rowmax = sf[0];
    __syncthreads();

    unsigned uthr = 0;
    int cut = len;                     // equals kept iff index <= cut
    if (do_topk) {
        unsigned prefix = 0, pmask = 0;
        int kk = k;
        for (int shift = 24; shift >= 0; shift -= 8) {
            hist[tid] = 0; __syncthreads();
            for (int s = tid; s < len; s += 256) {
                unsigned u = fkey(row[s]);
                if ((u & pmask) == prefix) atomicAdd(&hist[(u >> shift) & 255u], 1u);
            }
            __syncthreads();
            if (tid == 0) {
                int rem = kk; int b = 255;
                for (; b > 0; b--) { int c = (int)hist[b]; if (rem <= c) break; rem -= c; }
                s_sel = (unsigned)b; s_kk = rem;
            }
            __syncthreads();
            prefix |= (s_sel << shift);
            pmask  |= (0xFFu << shift);
            kk = s_kk;
            __syncthreads();
        }
        uthr = prefix;                 // key of k-th largest; kk = #equals to keep
        int e = 0;
        for (int s = tid; s < len; s += 256) if (fkey(row[s]) == uthr) e++;
        hist[tid] = (unsigned)e; __syncthreads();
        for (int off = 128; off > 0; off >>= 1) { if (tid < off) hist[tid] += hist[tid + off]; __syncthreads(); }
        int E = (int)hist[0];
        __syncthreads();
        if (E != kk) {                 // exact fp32 tie past cutoff: ~never
            if (tid == 0) {
                int c = 0, ci = -1;
                for (int s = 0; s < len; s++)
                    if (fkey(row[s]) == uthr) { c++; if (c == kk) { ci = s; break; } }
                s_cut = ci;
            }
            __syncthreads();
            cut = s_cut;
        }
    }

    float z = 0.f;
    for (int s = tid; s < len; s += 256) {
        float x = row[s];
        bool keep = true;
        if (do_topk) {
            unsigned u = fkey(x);
            keep = (u > uthr) || (u == uthr && s <= cut);
        }
        if (keep) z += expf(x - rowmax);
    }
    sf[tid] = z; __syncthreads();
    for (int off = 128; off > 0; off >>= 1) { if (tid < off) sf[tid] += sf[tid + off]; __syncthreads(); }
    float inv = 1.0f / sf[0];
    __syncthreads();

    for (int s = tid; s < S_LEN; s += 256) {
        float p = 0.f;
        if (s < len) {
            float x = row[s];
            bool keep = true;
            if (do_topk) {
                unsigned u = fkey(x);
                keep = (u > uthr) || (u == uthr && s <= cut);
            }
            if (keep) p = expf(x - rowmax) * inv;
        }
        row[s] = p;
    }
}

extern "C" void kernel_launch(void* const* d_in, const int* in_sizes, int n_in,
                              void* d_out, int out_size)
{
    const float* hidden = (const float*)d_in[0];
    const float* cosb   = (const float*)d_in[1];
    const float* sinb   = (const float*)d_in[2];
    const float* Wq     = (const float*)d_in[3];
    const float* Wk     = (const float*)d_in[4];
    const float* Wv     = (const float*)d_in[5];
    const float* Wo     = (const float*)d_in[6];
    float* out = (float*)d_out;

    float *Q, *K, *V, *P, *AO; int* F;
    cudaGetSymbolAddress((void**)&Q,  g_Q);
    cudaGetSymbolAddress((void**)&K,  g_K);
    cudaGetSymbolAddress((void**)&V,  g_V);
    cudaGetSymbolAddress((void**)&P,  g_P);
    cudaGetSymbolAddress((void**)&AO, g_AO);
    cudaGetSymbolAddress((void**)&F,  g_fetch);

    const float scale = 0.08838834764831845f; // 1/sqrt(128)
    dim3 blk(256);

    // Projections: X @ W^T
    sgemm_abT<<<dim3(D_DIM / 64, S_LEN / 64, 1), blk>>>(hidden, D_DIM, 0, Wq, D_DIM, 0, 1,
                                                        Q, D_DIM, 0, S_LEN, D_DIM, D_DIM, 1.f);
    sgemm_abT<<<dim3((NKV * HD) / 64, S_LEN / 64, 1), blk>>>(hidden, D_DIM, 0, Wk, D_DIM, 0, 1,
                                                             K, NKV * HD, 0, S_LEN, NKV * HD, D_DIM, 1.f);
    sgemm_abT<<<dim3((NKV * HD) / 64, S_LEN / 64, 1), blk>>>(hidden, D_DIM, 0, Wv, D_DIM, 0, 1,
                                                             V, NKV * HD, 0, S_LEN, NKV * HD, D_DIM, 1.f);
    // RoPE
    rope_kernel<<<dim3(S_LEN, NH),  64>>>(Q, NH,  cosb, sinb);
    rope_kernel<<<dim3(S_LEN, NKV), 64>>>(K, NKV, cosb, sinb);
    // Scores: per head h, scale * Q_h (1024x128) @ K_{h/4}^T
    sgemm_abT<<<dim3(S_LEN / 64, S_LEN / 64, NH), blk>>>(Q, D_DIM, HD, K, NKV * HD, HD, 4,
                                                         P, S_LEN, (long long)S_LEN * S_LEN,
                                                         S_LEN, S_LEN, HD, scale);
    // fetch_num per row
    stats_kernel<<<S_LEN, 256>>>(P, F);
    // top-k select + softmax -> probs in place (zeros where masked)
    softmax_select<<<dim3(S_LEN, NH), 256>>>(P, F);
    // Attention output: P_h (1024x1024) @ V_{h/4} (1024x128) -> AO[t][h*128+d]
    sgemm_ab<<<dim3(HD / 64, S_LEN / 64, NH), blk>>>(P, S_LEN, (long long)S_LEN * S_LEN,
                                                     V, NKV * HD, HD, 4,
                                                     AO, D_DIM, HD, S_LEN, HD, S_LEN, 1.f);
    // Output projection: AO @ Wo^T
    sgemm_abT<<<dim3(D_DIM / 64, S_LEN / 64, 1), blk>>>(AO, D_DIM, 0, Wo, D_DIM, 0, 1,
                                                        out, D_DIM, 0, S_LEN, D_DIM, D_DIM, 1.f);
    (void)in_sizes; (void)n_in; (void)out_size;
}

// round 2
// speedup vs baseline: 2.3442x; 2.3442x over previous
#include <cuda_runtime.h>
#include <cuda_bf16.h>
#include <math.h>

#define S_LEN 1024
#define D_DIM 4096
#define NH 32
#define NKV 8
#define HD 128
#define FETCH_MAX 204

#define BM 128
#define BN 128
#define BK 32
#define LDS 40   // bf16 element stride (80B: 16B-aligned, conflict-free ldmatrix phases)

// -------- scratch (device globals: allocation-free) --------
__device__ float g_Q[(size_t)S_LEN * D_DIM];
__device__ float g_K[(size_t)S_LEN * NKV * HD];
__device__ float g_V[(size_t)S_LEN * NKV * HD];
__device__ float g_VT[(size_t)NKV * HD * S_LEN];        // [kv][d][s]
__device__ float g_P[(size_t)NH * S_LEN * S_LEN];       // scores -> probs in place
__device__ float g_AO[(size_t)S_LEN * D_DIM];
__device__ int   g_fetch[S_LEN];

// ---------------- tensor-core primitives ----------------
__device__ __forceinline__ void ldsm_x4(unsigned r[4], const void* p) {
    unsigned a = (unsigned)__cvta_generic_to_shared(p);
    asm volatile("ldmatrix.sync.aligned.m8n8.x4.shared.b16 {%0,%1,%2,%3}, [%4];"
                 : "=r"(r[0]), "=r"(r[1]), "=r"(r[2]), "=r"(r[3]) : "r"(a));
}
__device__ __forceinline__ void mma16816(float* d, const unsigned* a, const unsigned* b) {
    asm volatile("mma.sync.aligned.m16n8k16.row.col.f32.bf16.bf16.f32 "
                 "{%0,%1,%2,%3}, {%4,%5,%6,%7}, {%8,%9}, {%0,%1,%2,%3};"
                 : "+f"(d[0]), "+f"(d[1]), "+f"(d[2]), "+f"(d[3])
                 : "r"(a[0]), "r"(a[1]), "r"(a[2]), "r"(a[3]), "r"(b[0]), "r"(b[1]));
}

// ============ split-bf16 GEMM: C = alpha * A(MxK) @ B(NxK)^T ============
// fp32 operands split to hi/lo bf16 in smem; acc += Ahi*Bhi + Ahi*Blo + Alo*Bhi
__global__ void __launch_bounds__(256) bgemm_abT(
    const float* __restrict__ A, int lda, long long sA,
    const float* __restrict__ B, int ldb, long long sB, int zdivB,
    float* __restrict__ C, int ldc, long long sC,
    int K, float alpha)
{
    A += (long long)blockIdx.z * sA;
    B += (long long)(blockIdx.z / zdivB) * sB;
    C += (long long)blockIdx.z * sC;

    __shared__ __align__(16) __nv_bfloat16 Ah[BM * LDS], Al[BM * LDS];
    __shared__ __align__(16) __nv_bfloat16 Bh[BN * LDS], Bl[BN * LDS];

    int tid = threadIdx.x;
    int lane = tid & 31, warp = tid >> 5;
    int wm = (warp & 1) << 6;   // 0 or 64
    int wn = (warp >> 1) << 5;  // 0,32,64,96
    int m0 = blockIdx.y * BM, n0 = blockIdx.x * BN;

    int lrow = tid >> 3;            // 0..31
    int lcol = (tid & 7) << 2;      // 0..28 step 4

    float acc[4][4][4];
    #pragma unroll
    for (int i = 0; i < 4; i++)
        #pragma unroll
        for (int j = 0; j < 4; j++)
            #pragma unroll
            for (int r = 0; r < 4; r++) acc[i][j][r] = 0.f;

    for (int k0 = 0; k0 < K; k0 += BK) {
        __syncthreads();
        #pragma unroll
        for (int r = 0; r < 4; r++) {
            int row = lrow + (r << 5);
            float4 a = *(const float4*)(A + (size_t)(m0 + row) * lda + k0 + lcol);
            float4 b = *(const float4*)(B + (size_t)(n0 + row) * ldb + k0 + lcol);
            __nv_bfloat16 hx = __float2bfloat16(a.x), hy = __float2bfloat16(a.y);
            __nv_bfloat16 hz = __float2bfloat16(a.z), hw = __float2bfloat16(a.w);
            __nv_bfloat16* pa = Ah + row * LDS + lcol;
            pa[0] = hx; pa[1] = hy; pa[2] = hz; pa[3] = hw;
            __nv_bfloat16* qa = Al + row * LDS + lcol;
            qa[0] = __float2bfloat16(a.x - __bfloat162float(hx));
            qa[1] = __float2bfloat16(a.y - __bfloat162float(hy));
            qa[2] = __float2bfloat16(a.z - __bfloat162float(hz));
            qa[3] = __float2bfloat16(a.w - __bfloat162float(hw));
            __nv_bfloat16 gx = __float2bfloat16(b.x), gy = __float2bfloat16(b.y);
            __nv_bfloat16 gz = __float2bfloat16(b.z), gw = __float2bfloat16(b.w);
            __nv_bfloat16* pb = Bh + row * LDS + lcol;
            pb[0] = gx; pb[1] = gy; pb[2] = gz; pb[3] = gw;
            __nv_bfloat16* qb = Bl + row * LDS + lcol;
            qb[0] = __float2bfloat16(b.x - __bfloat162float(gx));
            qb[1] = __float2bfloat16(b.y - __bfloat162float(gy));
            qb[2] = __float2bfloat16(b.z - __bfloat162float(gz));
            qb[3] = __float2bfloat16(b.w - __bfloat162float(gw));
        }
        __syncthreads();

        #pragma unroll
        for (int kk = 0; kk < BK; kk += 16) {
            #pragma unroll
            for (int pass = 0; pass < 3; pass++) {
                const __nv_bfloat16* As = (pass == 2) ? Al : Ah;
                const __nv_bfloat16* Bs = (pass == 1) ? Bl : Bh;
                unsigned af[4][4], bf[4][2];
                #pragma unroll
                for (int mi = 0; mi < 4; mi++) {
                    const __nv_bfloat16* p =
                        As + (wm + (mi << 4) + (lane & 15)) * LDS + kk + ((lane >> 4) << 3);
                    ldsm_x4(af[mi], p);
                }
                #pragma unroll
                for (int ni2 = 0; ni2 < 2; ni2++) {
                    unsigned r4[4];
                    const __nv_bfloat16* p =
                        Bs + (wn + (ni2 << 4) + ((lane >> 4) << 3) + (lane & 7)) * LDS
                           + kk + (((lane >> 3) & 1) << 3);
                    ldsm_x4(r4, p);
                    bf[ni2 * 2 + 0][0] = r4[0]; bf[ni2 * 2 + 0][1] = r4[1];
                    bf[ni2 * 2 + 1][0] = r4[2]; bf[ni2 * 2 + 1][1] = r4[3];
                }
                #pragma unroll
                for (int mi = 0; mi < 4; mi++)
                    #pragma unroll
                    for (int ni = 0; ni < 4; ni++)
                        mma16816(acc[mi][ni], af[mi], bf[ni]);
            }
        }
    }

    #pragma unroll
    for (int mi = 0; mi < 4; mi++) {
        #pragma unroll
        for (int ni = 0; ni < 4; ni++) {
            int row = m0 + wm + (mi << 4) + (lane >> 2);
            int col = n0 + wn + (ni << 3) + ((lane & 3) << 1);
            float2 v0 = make_float2(acc[mi][ni][0] * alpha, acc[mi][ni][1] * alpha);
            float2 v1 = make_float2(acc[mi][ni][2] * alpha, acc[mi][ni][3] * alpha);
            *(float2*)(C + (size_t)row * ldc + col) = v0;
            *(float2*)(C + (size_t)(row + 8) * ldc + col) = v1;
        }
    }
}

// =============== RoPE (in place) ===============
__global__ void __launch_bounds__(256) rope_kernel(float* __restrict__ X, int nheads,
                            const float* __restrict__ cosb, const float* __restrict__ sinb)
{
    int t = blockIdx.x, tid = threadIdx.x;
    __shared__ float cs[HD], sn[HD];
    if (tid < HD) { cs[tid] = cosb[t * HD + tid]; sn[tid] = sinb[t * HD + tid]; }
    __syncthreads();
    for (int idx = tid; idx < nheads * 64; idx += 256) {
        int h = idx >> 6, d = idx & 63;
        float* p = X + ((size_t)t * nheads + h) * HD;
        float x1 = p[d], x2 = p[d + 64];
        p[d]      = x1 * cs[d]      - x2 * sn[d];
        p[d + 64] = x2 * cs[d + 64] + x1 * sn[d + 64];
    }
}

// =============== V transpose: VT[kv][d][s] = V[s][kv*128+d] ===============
__global__ void transpose_v(const float* __restrict__ V, float* __restrict__ VT)
{
    __shared__ float tile[32][33];
    int kv = blockIdx.z;
    int s0 = blockIdx.x * 32, d0 = blockIdx.y * 32;
    int x = threadIdx.x, y = threadIdx.y;  // 32x8
    #pragma unroll
    for (int i = 0; i < 32; i += 8)
        tile[y + i][x] = V[(size_t)(s0 + y + i) * (NKV * HD) + kv * HD + d0 + x];
    __syncthreads();
    #pragma unroll
    for (int i = 0; i < 32; i += 8)
        VT[(size_t)kv * HD * S_LEN + (size_t)(d0 + y + i) * S_LEN + s0 + x] = tile[x][y + i];
}

// =============== per-row fetch_num ===============
__global__ void __launch_bounds__(256) stats_kernel(const float* __restrict__ P,
                                                    int* __restrict__ fetch)
{
    int t = blockIdx.x, tid = threadIdx.x;
    int len = t + 1;
    __shared__ float sf[256];
    __shared__ int si[256];
    const float* row0 = P + (size_t)t * S_LEN;
    float m = -3.4e38f;
    for (int s = tid; s < len; s += 256) m = fmaxf(m, row0[s]);
    sf[tid] = m; __syncthreads();
    for (int off = 128; off > 0; off >>= 1) { if (tid < off) sf[tid] = fmaxf(sf[tid], sf[tid + off]); __syncthreads(); }
    float thr = sf[0] - 5.0f;
    int cnt = 0;
    for (int h = 0; h < NH; h++) {
        const float* row = P + ((size_t)h * S_LEN + t) * S_LEN;
        for (int s = tid; s < len; s += 256) cnt += (row[s] >= thr) ? 1 : 0;
    }
    si[tid] = cnt; __syncthreads();
    for (int off = 128; off > 0; off >>= 1) { if (tid < off) si[tid] += si[tid + off]; __syncthreads(); }
    if (tid == 0) {
        int f = si[0] >> 5;
        fetch[t] = f < FETCH_MAX ? f : FETCH_MAX;
    }
}

__device__ __forceinline__ unsigned fkey(float f) {
    unsigned u = __float_as_uint(f);
    return (u & 0x80000000u) ? ~u : (u | 0x80000000u);
}

// ====== fused radix-select top-k + softmax (row cached in smem) ======
__global__ void __launch_bounds__(256) softmax_select(float* __restrict__ P,
                                                      const int* __restrict__ fetch)
{
    int t = blockIdx.x, h = blockIdx.y, tid = threadIdx.x;
    float* row = P + ((size_t)h * S_LEN + t) * S_LEN;
    __shared__ float srow[S_LEN];
    __shared__ float sf[256];
    __shared__ unsigned hist[256];
    __shared__ unsigned s_sel;
    __shared__ int s_kk, s_cut;

    int len = t + 1;
    bool do_topk = false;
    int k = 0;
    if (t >= FETCH_MAX) {
        k = fetch[t];
        if (k == 0) len = S_LEN;
        else do_topk = true;
    }

    for (int s = tid; s < len; s += 256) srow[s] = row[s];

    float m = -3.4e38f;
    for (int s = tid; s < len; s += 256) m = fmaxf(m, srow[s]);
    sf[tid] = m; __syncthreads();
    for (int off = 128; off > 0; off >>= 1) { if (tid < off) sf[tid] = fmaxf(sf[tid], sf[tid + off]); __syncthreads(); }
    float rowmax = sf[0];
    __syncthreads();

    unsigned uthr = 0;
    int cut = len;
    if (do_topk) {
        unsigned prefix = 0, pmask = 0;
        int kk = k;
        for (int shift = 24; shift >= 0; shift -= 8) {
            hist[tid] = 0; __syncthreads();
            for (int s = tid; s < len; s += 256) {
                unsigned u = fkey(srow[s]);
                if ((u & pmask) == prefix) atomicAdd(&hist[(u >> shift) & 255u], 1u);
            }
            __syncthreads();
            if (tid == 0) {
                int rem = kk; int b = 255;
                for (; b > 0; b--) { int c = (int)hist[b]; if (rem <= c) break; rem -= c; }
                s_sel = (unsigned)b; s_kk = rem;
            }
            __syncthreads();
            prefix |= (s_sel << shift);
            pmask  |= (0xFFu << shift);
            kk = s_kk;
            __syncthreads();
        }
        uthr = prefix;
        int e = 0;
        for (int s = tid; s < len; s += 256) if (fkey(srow[s]) == uthr) e++;
        hist[tid] = (unsigned)e; __syncthreads();
        for (int off = 128; off > 0; off >>= 1) { if (tid < off) hist[tid] += hist[tid + off]; __syncthreads(); }
        int E = (int)hist[0];
        __syncthreads();
        if (E != kk) {
            if (tid == 0) {
                int c = 0, ci = -1;
                for (int s = 0; s < len; s++)
                    if (fkey(srow[s]) == uthr) { c++; if (c == kk) { ci = s; break; } }
                s_cut = ci;
            }
            __syncthreads();
            cut = s_cut;
        }
    }

    float z = 0.f;
    for (int s = tid; s < len; s += 256) {
        float x = srow[s];
        bool keep = true;
        if (do_topk) {
            unsigned u = fkey(x);
            keep = (u > uthr) || (u == uthr && s <= cut);
        }
        if (keep) z += expf(x - rowmax);
    }
    sf[tid] = z; __syncthreads();
    for (int off = 128; off > 0; off >>= 1) { if (tid < off) sf[tid] += sf[tid + off]; __syncthreads(); }
    float inv = 1.0f / sf[0];
    __syncthreads();

    for (int s = tid; s < S_LEN; s += 256) {
        float p = 0.f;
        if (s < len) {
            float x = srow[s];
            bool keep = true;
            if (do_topk) {
                unsigned u = fkey(x);
                keep = (u > uthr) || (u == uthr && s <= cut);
            }
            if (keep) p = expf(x - rowmax) * inv;
        }
        row[s] = p;
    }
}

extern "C" void kernel_launch(void* const* d_in, const int* in_sizes, int n_in,
                              void* d_out, int out_size)
{
    const float* hidden = (const float*)d_in[0];
    const float* cosb   = (const float*)d_in[1];
    const float* sinb   = (const float*)d_in[2];
    const float* Wq     = (const float*)d_in[3];
    const float* Wk     = (const float*)d_in[4];
    const float* Wv     = (const float*)d_in[5];
    const float* Wo     = (const float*)d_in[6];
    float* out = (float*)d_out;

    float *Q, *K, *V, *VT, *P, *AO; int* F;
    cudaGetSymbolAddress((void**)&Q,  g_Q);
    cudaGetSymbolAddress((void**)&K,  g_K);
    cudaGetSymbolAddress((void**)&V,  g_V);
    cudaGetSymbolAddress((void**)&VT, g_VT);
    cudaGetSymbolAddress((void**)&P,  g_P);
    cudaGetSymbolAddress((void**)&AO, g_AO);
    cudaGetSymbolAddress((void**)&F,  g_fetch);

    const float scale = 0.08838834764831845f; // 1/sqrt(128)
    dim3 blk(256);

    // Projections: X @ W^T
    bgemm_abT<<<dim3(D_DIM / BN, S_LEN / BM, 1), blk>>>(hidden, D_DIM, 0, Wq, D_DIM, 0, 1,
                                                        Q, D_DIM, 0, D_DIM, 1.f);
    bgemm_abT<<<dim3((NKV * HD) / BN, S_LEN / BM, 1), blk>>>(hidden, D_DIM, 0, Wk, D_DIM, 0, 1,
                                                             K, NKV * HD, 0, D_DIM, 1.f);
    bgemm_abT<<<dim3((NKV * HD) / BN, S_LEN / BM, 1), blk>>>(hidden, D_DIM, 0, Wv, D_DIM, 0, 1,
                                                             V, NKV * HD, 0, D_DIM, 1.f);
    // RoPE
    rope_kernel<<<S_LEN, 256>>>(Q, NH,  cosb, sinb);
    rope_kernel<<<S_LEN, 256>>>(K, NKV, cosb, sinb);
    // V transpose for PV GEMM
    transpose_v<<<dim3(S_LEN / 32, HD / 32, NKV), dim3(32, 8)>>>(V, VT);
    // Scores: per head, scale * Q_h @ K_kv^T
    bgemm_abT<<<dim3(S_LEN / BN, S_LEN / BM, NH), blk>>>(Q, D_DIM, HD, K, NKV * HD, HD, 4,
                                                         P, S_LEN, (long long)S_LEN * S_LEN,
                                                         HD, scale);
    // fetch_num per row
    stats_kernel<<<S_LEN, 256>>>(P, F);
    // top-k select + softmax
    softmax_select<<<dim3(S_LEN, NH), 256>>>(P, F);
    // PV: P_h @ VT_kv^T -> AO
    bgemm_abT<<<dim3(HD / BN, S_LEN / BM, NH), blk>>>(P, S_LEN, (long long)S_LEN * S_LEN,
                                                      VT, S_LEN, (long long)HD * S_LEN, 4,
                                                      AO, D_DIM, HD, S_LEN, 1.f);
    // Output projection: AO @ Wo^T
    bgemm_abT<<<dim3(D_DIM / BN, S_LEN / BM, 1), blk>>>(AO, D_DIM, 0, Wo, D_DIM, 0, 1,
                                                        out, D_DIM, 0, D_DIM, 1.f);
    (void)in_sizes; (void)n_in; (void)out_size;
}